// round 7
// baseline (speedup 1.0000x reference)
#include <cuda_runtime.h>
#include <math.h>

#define DD 1024

// ---------------- static device storage (no allocation allowed) ----------------
static __device__ double d_H[32 * 32];
static __device__ double d_g;
static __device__ double d_CS[DD * DD];
static __device__ double d_CA[DD * DD];
static __device__ float  d_M0[DD * DD];     // P
static __device__ float  d_M1[DD * DD];     // P2
static __device__ float  d_M2[DD * DD];     // X
static __device__ float  d_M3[DD * DD];     // E / U ping
static __device__ float  d_M4[DD * DD];     // pong
static __device__ float  d_u[DD];           // col 16 of U^(2^(nd-2))
static __device__ float  d_u2[DD];          // col 16 of U^(2^(nd-1))
static __device__ float  d_Arows[2048 * DD];

// ---------------- model: H on reduced 32-dim space ----------------
__device__ __forceinline__ double qmat(int r, int c) {
    if (c == r + 1) return sqrt((double)c * 0.5);
    if (r == c + 1) return sqrt((double)r * 0.5);
    return 0.0;
}

__global__ void k_build_H(const float* log_g) {
    int a = threadIdx.x;
    if (a == 0) d_g = (double)expf(log_g[0]);
    int i = a >> 5, j = a & 31;
    int si = i >> 4, vi = i & 15, v6i = vi >> 2, v10i = vi & 3;
    int sj = j >> 4, vj = j & 15, v6j = vj >> 2, v10j = vj & 3;
    const double CM2EV = 0.00012398419;
    const double E_S1 = 3.995, E_S2 = 4.9183;
    const double om6a = 596.0 * CM2EV, om10a = 919.0 * CM2EV;
    const double kap1 = -0.0964, kap2 = 0.1193;
    const double lam = 0.1825, gam = -0.018;
    double val = 0.0;
    if (si == sj) {
        if (vi == vj) val += (si == 0 ? E_S1 : E_S2) + om6a * v6i + om10a * v10i;
        if (v10i == v10j) val += (si == 0 ? kap1 : kap2) * qmat(v6i, v6j);
    } else {
        if (v6i == v6j) {
            double q2 = 0.0;
            #pragma unroll
            for (int m = 0; m < 4; m++) q2 += qmat(v10i, m) * qmat(m, v10j);
            val += lam * qmat(v10i, v10j) + gam * q2;
        }
    }
    d_H[i * 32 + j] = val;
}

// ---------------- real hermitian basis bookkeeping ----------------
__device__ __forceinline__ void decode_basis(int m, int& type, int& p, int& q) {
    if (m < 32) { type = 0; p = q = m; return; }
    int pi = (m < 528) ? (m - 32) : (m - 528);
    type = (m < 528) ? 1 : 2;
    int r = 0, cnt = 31;
    while (pi >= cnt) { pi -= cnt; r++; cnt--; }
    p = r; q = r + 1 + pi;
}

__global__ void k_stageG() {
    int n = blockIdx.x;
    int ab = threadIdx.x;
    int a = ab >> 5, b = ab & 31;
    int type, p, q;
    decode_basis(n, type, p, q);
    double v = (type == 0) ? 1.0 : 0.70710678118654752440;
    int nc = (type == 0) ? 1 : 2;
    int cc[2] = { p, q };
    int dd[2] = { q, p };
    double ww[2] = { v, (type == 2) ? -v : v };

    const double g = d_g;
    double HX = 0.0, XH = 0.0, Xab = 0.0, X16 = 0.0;
    for (int e = 0; e < nc; e++) {
        if (dd[e] == b) HX += d_H[a * 32 + cc[e]] * ww[e];
        if (cc[e] == a) XH += ww[e] * d_H[dd[e] * 32 + b];
        if (cc[e] == a && dd[e] == b) Xab += ww[e];
        if (a < 16 && b < 16 && cc[e] == a + 16 && dd[e] == b + 16) X16 += ww[e];
    }
    double diss = g * (X16 - 0.5 * Xab * (double)((a >= 16) + (b >= 16)));
    double cs, ca;
    if (type == 2) { cs = XH - HX; ca = diss; }
    else           { ca = HX - XH; cs = diss; }
    d_CS[n * DD + ab] = cs;
    d_CA[n * DD + ab] = ca;
}

__global__ void k_project() {
    int idx = blockIdx.x * 1024 + threadIdx.x;
    int m = idx >> 10, n = idx & 1023;
    int type, i, j;
    decode_basis(m, type, i, j);
    const double SQ2 = 1.41421356237309504880;
    double val;
    if (type == 0)      val = d_CS[n * DD + i * 33];
    else if (type == 1) val = SQ2 * d_CS[n * DD + i * 32 + j];
    else                val = SQ2 * d_CA[n * DD + i * 32 + j];
    const double scale = (1.0 / 0.6582119569) / 256.0;
    d_M0[m * DD + n] = (float)(val * scale);
}

__global__ void k_Ainit() {
    int r = blockIdx.x, c = threadIdx.x;
    float v = 0.0f;
    if (r == 0 && c < 16) v = 1.0f;
    if (r == 1 && c >= 16 && c < 32) v = 1.0f;
    d_Arows[r * DD + c] = v;
}

__global__ void k_extract(float* __restrict__ out, int n) {
    int t = blockIdx.x * blockDim.x + threadIdx.x;
    if (t >= n) return;
    out[t] = 0.0f;
    out[n + t]     = d_Arows[(size_t)(2 * t) * DD + 16];
    out[2 * n + t] = d_Arows[(size_t)(2 * t + 1) * DD + 16];
}

// ---------------- packed f32x2 helpers ----------------
__device__ __forceinline__ void ffma2(unsigned long long& acc,
                                      unsigned long long a, unsigned long long b) {
    asm("fma.rn.f32x2 %0, %1, %2, %0;" : "+l"(acc) : "l"(a), "l"(b));
}
__device__ __forceinline__ void unpack2(unsigned long long v, float& lo, float& hi) {
    unsigned a, b;
    asm("mov.b64 {%0, %1}, %2;" : "=r"(a), "=r"(b) : "l"(v));
    lo = __uint_as_float(a); hi = __uint_as_float(b);
}

// ---------------- GEMM tile body: C(MxDD)=A@B, 64x64 tile, 256 thr, 4x4, FFMA2 ----------------
// sA staged PRE-DUPLICATED: sAd[k][r] = (A[r,k], A[r,k]) so the inner loop has
// zero packing ops: 3x LDS.128 + 8x FFMA2 per kk.
// mode 0: C = acc
// mode 1: C = acc (=P2); X = 0.5*I + (1/6)*P + (1/24)*acc
// mode 2: C = acc + P + I
#define GBK 16
__device__ __forceinline__ void gemm_tile(
    const float* __restrict__ A, const float* __restrict__ B, float* __restrict__ C,
    int M, int row0, int bx, int mode,
    const float* __restrict__ P, float* __restrict__ X)
{
    __shared__ float2 sAd[GBK][64];   // duplicated, transposed A tile (8KB)
    __shared__ float  sB[GBK][64];    // B tile (4KB)
    int t = threadIdx.x;
    int tx = t & 15, ty = t >> 4;

    unsigned long long acc[4][2];
    #pragma unroll
    for (int i = 0; i < 4; i++) { acc[i][0] = 0ULL; acc[i][1] = 0ULL; }

    for (int kt = 0; kt < DD; kt += GBK) {
        {   // stage A tile: transposed + duplicated
            int r = t >> 2, kc = t & 3;
            float4 v = make_float4(0.f, 0.f, 0.f, 0.f);
            if (row0 + r < M)
                v = *(const float4*)&A[(size_t)(row0 + r) * DD + kt + kc * 4];
            sAd[kc * 4 + 0][r] = make_float2(v.x, v.x);
            sAd[kc * 4 + 1][r] = make_float2(v.y, v.y);
            sAd[kc * 4 + 2][r] = make_float2(v.z, v.z);
            sAd[kc * 4 + 3][r] = make_float2(v.w, v.w);
        }
        {   // stage B tile
            int k = t >> 4, nc = t & 15;
            *(float4*)&sB[k][nc * 4] =
                *(const float4*)&B[(size_t)(kt + k) * DD + bx * 64 + nc * 4];
        }
        __syncthreads();
        #pragma unroll
        for (int kk = 0; kk < GBK; kk++) {
            ulonglong2 a01 = *(const ulonglong2*)&sAd[kk][ty * 4];
            ulonglong2 a23 = *(const ulonglong2*)&sAd[kk][ty * 4 + 2];
            ulonglong2 bv  = *(const ulonglong2*)&sB[kk][tx * 4];
            ffma2(acc[0][0], a01.x, bv.x); ffma2(acc[0][1], a01.x, bv.y);
            ffma2(acc[1][0], a01.y, bv.x); ffma2(acc[1][1], a01.y, bv.y);
            ffma2(acc[2][0], a23.x, bv.x); ffma2(acc[2][1], a23.x, bv.y);
            ffma2(acc[3][0], a23.y, bv.x); ffma2(acc[3][1], a23.y, bv.y);
        }
        __syncthreads();
    }

    #pragma unroll
    for (int i = 0; i < 4; i++) {
        int r = row0 + ty * 4 + i;
        if (r >= M) continue;
        float v[4];
        unpack2(acc[i][0], v[0], v[1]);
        unpack2(acc[i][1], v[2], v[3]);
        int c0 = bx * 64 + tx * 4;
        size_t base = (size_t)r * DD + c0;
        if (mode == 0) {
            *(float4*)&C[base] = make_float4(v[0], v[1], v[2], v[3]);
        } else if (mode == 1) {
            *(float4*)&C[base] = make_float4(v[0], v[1], v[2], v[3]);
            float x[4];
            #pragma unroll
            for (int j = 0; j < 4; j++) {
                x[j] = (1.0f/6.0f) * P[base + j] + (1.0f/24.0f) * v[j];
                if (r == c0 + j) x[j] += 0.5f;
            }
            *(float4*)&X[base] = make_float4(x[0], x[1], x[2], x[3]);
        } else {
            float e[4];
            #pragma unroll
            for (int j = 0; j < 4; j++) {
                e[j] = v[j] + P[base + j];
                if (r == c0 + j) e[j] += 1.0f;
            }
            *(float4*)&C[base] = make_float4(e[0], e[1], e[2], e[3]);
        }
    }
}

__global__ void __launch_bounds__(256) k_gemm(
    const float* __restrict__ A, const float* __restrict__ B, float* __restrict__ C,
    int M, int mode, const float* __restrict__ P, float* __restrict__ X)
{
    gemm_tile(A, B, C, M, blockIdx.y * 64, blockIdx.x, mode, P, X);
}

// fused: blocks by<16 do Bn = Bc@Bc; by>=16 do Adst = Ar@Bc (M=rows)
__global__ void __launch_bounds__(256) k_sq_dbl(
    const float* __restrict__ Bc, float* __restrict__ Bn,
    const float* __restrict__ Ar, float* __restrict__ Adst, int rows)
{
    if (blockIdx.y < 16)
        gemm_tile(Bc, Bc, Bn, DD, blockIdx.y * 64, blockIdx.x, 0, 0, 0);
    else
        gemm_tile(Ar, Bc, Adst, rows, (blockIdx.y - 16) * 64, blockIdx.x, 0, 0, 0);
}

// grab column 16 of Bc
__global__ void k_getcol(const float* __restrict__ Bc) {
    d_u[threadIdx.x] = Bc[(size_t)threadIdx.x * DD + 16];
}

// matvec: d_u2 = Bc @ d_u   (gives col 16 of Bc^2 without a full squaring)
__global__ void __launch_bounds__(256) k_matvec(const float* __restrict__ Bc) {
    __shared__ float red[256];
    int r = blockIdx.x, t = threadIdx.x;
    float s = 0.0f;
    const float* row = &Bc[(size_t)r * DD];
    for (int k = t; k < DD; k += 256)
        s = fmaf(row[k], d_u[k], s);
    red[t] = s;
    __syncthreads();
    for (int w = 128; w > 0; w >>= 1) {
        if (t < w) red[t] += red[t + w];
        __syncthreads();
    }
    if (t == 0) d_u2[r] = red[0];
}

// final doubling, column 16 only: Ar[rows+r][16] = dot(Ar[r,:], u2)
__global__ void __launch_bounds__(256) k_gemv(int rows) {
    __shared__ float red[256];
    int r = blockIdx.x, t = threadIdx.x;
    float s = 0.0f;
    const float* row = &d_Arows[(size_t)r * DD];
    for (int k = t; k < DD; k += 256)
        s = fmaf(row[k], d_u2[k], s);
    red[t] = s;
    __syncthreads();
    for (int w = 128; w > 0; w >>= 1) {
        if (t < w) red[t] += red[t + w];
        __syncthreads();
    }
    if (t == 0) d_Arows[(size_t)(rows + r) * DD + 16] = red[0];
}

// ---------------- driver ----------------
extern "C" void kernel_launch(void* const* d_in, const int* in_sizes, int n_in,
                              void* d_out, int out_size) {
    const float* log_g = (const float*)d_in[0];
    int n_steps = out_size / 3;
    if (n_steps < 1) n_steps = 1;
    if (n_steps > 1024) n_steps = 1024;

    void *p0, *p1, *p2, *p3, *p4, *pA;
    cudaGetSymbolAddress(&p0, d_M0);
    cudaGetSymbolAddress(&p1, d_M1);
    cudaGetSymbolAddress(&p2, d_M2);
    cudaGetSymbolAddress(&p3, d_M3);
    cudaGetSymbolAddress(&p4, d_M4);
    cudaGetSymbolAddress(&pA, d_Arows);
    float *M0 = (float*)p0, *M1 = (float*)p1, *M2 = (float*)p2,
          *M3 = (float*)p3, *M4 = (float*)p4, *Ar = (float*)pA;

    // Phase 0: build generator P (fp32) in M0
    k_build_H<<<1, 1024>>>(log_g);
    k_stageG<<<1024, 1024>>>();
    k_project<<<1024, 1024>>>();

    dim3 gfull(16, 16);
    // Phase 1: expm = order-4 Taylor (PS) + 8 squarings
    k_gemm<<<gfull, 256>>>(M0, M0, M1, DD, 1, M0, M2);  // P2 (+X fused)
    k_gemm<<<gfull, 256>>>(M1, M2, M3, DD, 2, M0, 0);   // E = P2@X + P + I
    float* Ec = M3; float* Eo = M4;
    for (int s = 0; s < 8; s++) {
        k_gemm<<<gfull, 256>>>(Ec, Ec, Eo, DD, 0, 0, 0);
        float* tmp = Ec; Ec = Eo; Eo = tmp;
    }
    // Ec holds U

    // Phase 2: time doubling
    k_Ainit<<<2, 1024>>>();
    int nd = 0;
    while ((1 << nd) < n_steps) nd++;
    if (nd > 10) nd = 10;

    float* Bc = Ec;
    float* Bn = Eo;
    int rows = 2;
    if (nd >= 3) {
        // fused squaring + doubling for j = 0 .. nd-3
        for (int kd = 0; kd + 2 < nd; kd++) {
            int dbl_tiles = (rows + 63) / 64;
            k_sq_dbl<<<dim3(16, 16 + dbl_tiles), 256>>>(
                Bc, Bn, Ar, Ar + (size_t)rows * DD, rows);
            rows <<= 1;
            float* tmp = Bc; Bc = Bn; Bn = tmp;
        }
        // j = nd-2: doubling only (no squaring needed)
        k_gemm<<<dim3(16, (rows + 63) / 64), 256>>>(
            Ar, Bc, Ar + (size_t)rows * DD, rows, 0, 0, 0);
        rows <<= 1;
        // j = nd-1: only col 16 of the new rows is ever read.
        // u2 = col16 of Bc^2, via matvec (replaces a full squaring GEMM).
        k_getcol<<<1, 1024>>>(Bc);
        k_matvec<<<DD, 256>>>(Bc);
        k_gemv<<<rows, 256>>>(rows);
    } else {
        for (int kd = 0; kd < nd; kd++) {
            k_gemm<<<dim3(16, (rows + 63) / 64), 256>>>(
                Ar, Bc, Ar + (size_t)rows * DD, rows, 0, 0, 0);
            rows <<= 1;
            if (kd < nd - 1) {
                k_gemm<<<gfull, 256>>>(Bc, Bc, Bn, DD, 0, 0, 0);
                float* tmp = Bc; Bc = Bn; Bn = tmp;
            }
        }
    }

    // Phase 3: extract populations
    k_extract<<<(n_steps + 255) / 256, 256>>>((float*)d_out, n_steps);
}

// round 8
// speedup vs baseline: 1.4729x; 1.4729x over previous
#include <cuda_runtime.h>
#include <math.h>

#define DD 1024
#define GBK 16

// ---------------- static device storage (no allocation allowed) ----------------
static __device__ double d_H[32 * 32];
static __device__ double d_g;
static __device__ double d_CS[DD * DD];
static __device__ double d_CA[DD * DD];
static __device__ float  d_M0[DD * DD];     // P
static __device__ float  d_M1[DD * DD];     // P2 / E / ping
static __device__ float  d_M2[DD * DD];     // P3
static __device__ float  d_M3[DD * DD];     // W / U / pong
static __device__ float  d_M4[DD * DD];     // P4
static __device__ float  d_u[DD];
static __device__ float  d_u2[DD];
static __device__ float  d_Arows[2048 * DD];

// ---------------- model: H on reduced 32-dim space ----------------
__device__ __forceinline__ double qmat(int r, int c) {
    if (c == r + 1) return sqrt((double)c * 0.5);
    if (r == c + 1) return sqrt((double)r * 0.5);
    return 0.0;
}

__global__ void k_build_H(const float* log_g) {
    int a = threadIdx.x;
    if (a == 0) d_g = (double)expf(log_g[0]);
    int i = a >> 5, j = a & 31;
    int si = i >> 4, vi = i & 15, v6i = vi >> 2, v10i = vi & 3;
    int sj = j >> 4, vj = j & 15, v6j = vj >> 2, v10j = vj & 3;
    const double CM2EV = 0.00012398419;
    const double E_S1 = 3.995, E_S2 = 4.9183;
    const double om6a = 596.0 * CM2EV, om10a = 919.0 * CM2EV;
    const double kap1 = -0.0964, kap2 = 0.1193;
    const double lam = 0.1825, gam = -0.018;
    double val = 0.0;
    if (si == sj) {
        if (vi == vj) val += (si == 0 ? E_S1 : E_S2) + om6a * v6i + om10a * v10i;
        if (v10i == v10j) val += (si == 0 ? kap1 : kap2) * qmat(v6i, v6j);
    } else {
        if (v6i == v6j) {
            double q2 = 0.0;
            #pragma unroll
            for (int m = 0; m < 4; m++) q2 += qmat(v10i, m) * qmat(m, v10j);
            val += lam * qmat(v10i, v10j) + gam * q2;
        }
    }
    d_H[i * 32 + j] = val;
}

// ---------------- real hermitian basis bookkeeping ----------------
__device__ __forceinline__ void decode_basis(int m, int& type, int& p, int& q) {
    if (m < 32) { type = 0; p = q = m; return; }
    int pi = (m < 528) ? (m - 32) : (m - 528);
    type = (m < 528) ? 1 : 2;
    int r = 0, cnt = 31;
    while (pi >= cnt) { pi -= cnt; r++; cnt--; }
    p = r; q = r + 1 + pi;
}

__global__ void k_stageG() {
    int n = blockIdx.x;
    int ab = threadIdx.x;
    int a = ab >> 5, b = ab & 31;
    int type, p, q;
    decode_basis(n, type, p, q);
    double v = (type == 0) ? 1.0 : 0.70710678118654752440;
    int nc = (type == 0) ? 1 : 2;
    int cc[2] = { p, q };
    int dd[2] = { q, p };
    double ww[2] = { v, (type == 2) ? -v : v };

    const double g = d_g;
    double HX = 0.0, XH = 0.0, Xab = 0.0, X16 = 0.0;
    for (int e = 0; e < nc; e++) {
        if (dd[e] == b) HX += d_H[a * 32 + cc[e]] * ww[e];
        if (cc[e] == a) XH += ww[e] * d_H[dd[e] * 32 + b];
        if (cc[e] == a && dd[e] == b) Xab += ww[e];
        if (a < 16 && b < 16 && cc[e] == a + 16 && dd[e] == b + 16) X16 += ww[e];
    }
    double diss = g * (X16 - 0.5 * Xab * (double)((a >= 16) + (b >= 16)));
    double cs, ca;
    if (type == 2) { cs = XH - HX; ca = diss; }
    else           { ca = HX - XH; cs = diss; }
    d_CS[n * DD + ab] = cs;
    d_CA[n * DD + ab] = ca;
}

// scale = (DT/HBAR) / 2^3   (s = 3 squarings for expm)
__global__ void k_project() {
    int idx = blockIdx.x * 1024 + threadIdx.x;
    int m = idx >> 10, n = idx & 1023;
    int type, i, j;
    decode_basis(m, type, i, j);
    const double SQ2 = 1.41421356237309504880;
    double val;
    if (type == 0)      val = d_CS[n * DD + i * 33];
    else if (type == 1) val = SQ2 * d_CS[n * DD + i * 32 + j];
    else                val = SQ2 * d_CA[n * DD + i * 32 + j];
    const double scale = (1.0 / 0.6582119569) / 8.0;
    d_M0[m * DD + n] = (float)(val * scale);
}

__global__ void k_Ainit() {
    int r = blockIdx.x, c = threadIdx.x;
    float v = 0.0f;
    if (r == 0 && c < 16) v = 1.0f;
    if (r == 1 && c >= 16 && c < 32) v = 1.0f;
    d_Arows[r * DD + c] = v;
}

__global__ void k_extract(float* __restrict__ out, int n) {
    int t = blockIdx.x * blockDim.x + threadIdx.x;
    if (t >= n) return;
    out[t] = 0.0f;
    out[n + t]     = d_Arows[(size_t)(2 * t) * DD + 16];
    out[2 * n + t] = d_Arows[(size_t)(2 * t + 1) * DD + 16];
}

// ---------------- packed f32x2 helpers ----------------
__device__ __forceinline__ void ffma2(unsigned long long& acc,
                                      unsigned long long a, unsigned long long b) {
    asm("fma.rn.f32x2 %0, %1, %2, %0;" : "+l"(acc) : "l"(a), "l"(b));
}
__device__ __forceinline__ unsigned long long pack2(float x) {
    unsigned long long r; unsigned u = __float_as_uint(x);
    asm("mov.b64 %0, {%1, %1};" : "=l"(r) : "r"(u));
    return r;
}
__device__ __forceinline__ void unpack2(unsigned long long v, float& lo, float& hi) {
    unsigned a, b;
    asm("mov.b64 {%0, %1}, %2;" : "=r"(a), "=r"(b) : "l"(v));
    lo = __uint_as_float(a); hi = __uint_as_float(b);
}

// ---------------- GEMM: C(MxDD)=A@B; 64x64 tile; 512 thr = 2 K-teams of 256 ----------------
// Team 0 sums k in [0,512), team 1 sums k in [512,1024); deterministic lo+hi combine.
// mode 0: C = v
// mode 1: C(=P4) = v;  W = I/24 + P/120 + P2/720 + P3/5040 + v/40320
// mode 2: C(=E)  = v + I + P + P2/2 + P3/6
__device__ __forceinline__ void gemm_tile512(
    const float* __restrict__ A, const float* __restrict__ B, float* __restrict__ C,
    int M, int row0, int bx, int mode,
    const float* __restrict__ P, const float* __restrict__ P2,
    const float* __restrict__ P3, float* __restrict__ W)
{
    __shared__ float smem[2][2][GBK][64];     // [team][A|B][k][64] = 16KB
    float* pad = &smem[0][0][0][0];           // aliased 64x64 partial pad (safe: after final sync)
    int tid = threadIdx.x;
    int team = tid >> 8;
    int t = tid & 255;
    int tx = t & 15, ty = t >> 4;
    int k0 = team << 9;
    float (*sA)[64] = smem[team][0];
    float (*sB)[64] = smem[team][1];

    unsigned long long acc[4][2];
    #pragma unroll
    for (int i = 0; i < 4; i++) { acc[i][0] = 0ULL; acc[i][1] = 0ULL; }

    for (int kt = 0; kt < 512; kt += GBK) {
        {   // stage A tile (transposed)
            int r = t >> 2, kc = t & 3;
            float4 v = make_float4(0.f, 0.f, 0.f, 0.f);
            if (row0 + r < M)
                v = *(const float4*)&A[(size_t)(row0 + r) * DD + k0 + kt + kc * 4];
            sA[kc * 4 + 0][r] = v.x;
            sA[kc * 4 + 1][r] = v.y;
            sA[kc * 4 + 2][r] = v.z;
            sA[kc * 4 + 3][r] = v.w;
        }
        {   // stage B tile
            int k = t >> 4, nc = t & 15;
            *(float4*)&sB[k][nc * 4] =
                *(const float4*)&B[(size_t)(k0 + kt + k) * DD + bx * 64 + nc * 4];
        }
        __syncthreads();
        #pragma unroll
        for (int kk = 0; kk < GBK; kk++) {
            float4 av = *(const float4*)&sA[kk][ty * 4];
            ulonglong2 bv = *(const ulonglong2*)&sB[kk][tx * 4];
            unsigned long long a0 = pack2(av.x), a1 = pack2(av.y),
                               a2 = pack2(av.z), a3 = pack2(av.w);
            ffma2(acc[0][0], a0, bv.x); ffma2(acc[0][1], a0, bv.y);
            ffma2(acc[1][0], a1, bv.x); ffma2(acc[1][1], a1, bv.y);
            ffma2(acc[2][0], a2, bv.x); ffma2(acc[2][1], a2, bv.y);
            ffma2(acc[3][0], a3, bv.x); ffma2(acc[3][1], a3, bv.y);
        }
        __syncthreads();
    }

    // combine: team 1 deposits its partials, team 0 adds (lo-half + hi-half, deterministic)
    if (team == 1) {
        #pragma unroll
        for (int i = 0; i < 4; i++) {
            float v[4];
            unpack2(acc[i][0], v[0], v[1]);
            unpack2(acc[i][1], v[2], v[3]);
            *(float4*)&pad[(ty * 4 + i) * 64 + tx * 4] = make_float4(v[0], v[1], v[2], v[3]);
        }
    }
    __syncthreads();
    if (team == 0) {
        #pragma unroll
        for (int i = 0; i < 4; i++) {
            int r = row0 + ty * 4 + i;
            if (r >= M) continue;
            float v[4];
            unpack2(acc[i][0], v[0], v[1]);
            unpack2(acc[i][1], v[2], v[3]);
            float4 pv = *(const float4*)&pad[(ty * 4 + i) * 64 + tx * 4];
            v[0] += pv.x; v[1] += pv.y; v[2] += pv.z; v[3] += pv.w;
            int c0 = bx * 64 + tx * 4;
            size_t base = (size_t)r * DD + c0;
            if (mode == 0) {
                *(float4*)&C[base] = make_float4(v[0], v[1], v[2], v[3]);
            } else if (mode == 1) {
                *(float4*)&C[base] = make_float4(v[0], v[1], v[2], v[3]);
                float w[4];
                #pragma unroll
                for (int j = 0; j < 4; j++) {
                    w[j] = (1.0f/120.0f) * P[base + j] + (1.0f/720.0f) * P2[base + j]
                         + (1.0f/5040.0f) * P3[base + j] + (1.0f/40320.0f) * v[j];
                    if (r == c0 + j) w[j] += 1.0f/24.0f;
                }
                *(float4*)&W[base] = make_float4(w[0], w[1], w[2], w[3]);
            } else {
                float e[4];
                #pragma unroll
                for (int j = 0; j < 4; j++) {
                    e[j] = v[j] + P[base + j] + 0.5f * P2[base + j]
                         + (1.0f/6.0f) * P3[base + j];
                    if (r == c0 + j) e[j] += 1.0f;
                }
                *(float4*)&C[base] = make_float4(e[0], e[1], e[2], e[3]);
            }
        }
    }
}

__global__ void __launch_bounds__(512, 2) k_gemm512(
    const float* __restrict__ A, const float* __restrict__ B, float* __restrict__ C,
    int M, int mode, const float* __restrict__ P, const float* __restrict__ P2,
    const float* __restrict__ P3, float* __restrict__ W)
{
    gemm_tile512(A, B, C, M, blockIdx.y * 64, blockIdx.x, mode, P, P2, P3, W);
}

// fused: by<16 squares (Bn = Bc@Bc); by>=16 doubles rows (Adst = Ar@Bc)
__global__ void __launch_bounds__(512, 2) k_sq_dbl512(
    const float* __restrict__ Bc, float* __restrict__ Bn,
    const float* __restrict__ Ar, float* __restrict__ Adst, int rows)
{
    if (blockIdx.y < 16)
        gemm_tile512(Bc, Bc, Bn, DD, blockIdx.y * 64, blockIdx.x, 0, 0, 0, 0, 0);
    else
        gemm_tile512(Ar, Bc, Adst, rows, (blockIdx.y - 16) * 64, blockIdx.x, 0, 0, 0, 0, 0);
}

__global__ void k_getcol(const float* __restrict__ Bc) {
    d_u[threadIdx.x] = Bc[(size_t)threadIdx.x * DD + 16];
}

__global__ void __launch_bounds__(256) k_matvec(const float* __restrict__ Bc) {
    __shared__ float red[256];
    int r = blockIdx.x, t = threadIdx.x;
    float s = 0.0f;
    const float* row = &Bc[(size_t)r * DD];
    for (int k = t; k < DD; k += 256)
        s = fmaf(row[k], d_u[k], s);
    red[t] = s;
    __syncthreads();
    for (int w = 128; w > 0; w >>= 1) {
        if (t < w) red[t] += red[t + w];
        __syncthreads();
    }
    if (t == 0) d_u2[r] = red[0];
}

__global__ void __launch_bounds__(256) k_gemv(int rows) {
    __shared__ float red[256];
    int r = blockIdx.x, t = threadIdx.x;
    float s = 0.0f;
    const float* row = &d_Arows[(size_t)r * DD];
    for (int k = t; k < DD; k += 256)
        s = fmaf(row[k], d_u2[k], s);
    red[t] = s;
    __syncthreads();
    for (int w = 128; w > 0; w >>= 1) {
        if (t < w) red[t] += red[t + w];
        __syncthreads();
    }
    if (t == 0) d_Arows[(size_t)(rows + r) * DD + 16] = red[0];
}

// ---------------- driver ----------------
extern "C" void kernel_launch(void* const* d_in, const int* in_sizes, int n_in,
                              void* d_out, int out_size) {
    const float* log_g = (const float*)d_in[0];
    int n_steps = out_size / 3;
    if (n_steps < 1) n_steps = 1;
    if (n_steps > 1024) n_steps = 1024;

    void *p0, *p1, *p2, *p3, *p4, *pA;
    cudaGetSymbolAddress(&p0, d_M0);
    cudaGetSymbolAddress(&p1, d_M1);
    cudaGetSymbolAddress(&p2, d_M2);
    cudaGetSymbolAddress(&p3, d_M3);
    cudaGetSymbolAddress(&p4, d_M4);
    cudaGetSymbolAddress(&pA, d_Arows);
    float *M0 = (float*)p0, *M1 = (float*)p1, *M2 = (float*)p2,
          *M3 = (float*)p3, *M4 = (float*)p4, *Ar = (float*)pA;

    // Phase 0: build generator P (fp32, scale 1/(8*HBAR)) in M0
    k_build_H<<<1, 1024>>>(log_g);
    k_stageG<<<1024, 1024>>>();
    k_project<<<1024, 1024>>>();

    dim3 gfull(16, 16);
    // Phase 1: expm = order-8 Taylor (Paterson-Stockmeyer) + 3 squarings
    k_gemm512<<<gfull, 512>>>(M0, M0, M1, DD, 0, 0, 0, 0, 0);       // P2
    k_gemm512<<<gfull, 512>>>(M1, M0, M2, DD, 0, 0, 0, 0, 0);       // P3
    k_gemm512<<<gfull, 512>>>(M1, M1, M4, DD, 1, M0, M1, M2, M3);   // P4 -> M4, W -> M3
    k_gemm512<<<gfull, 512>>>(M4, M3, M1, DD, 2, M0, M1, M2, 0);    // E = P4@W + C1 -> M1
    k_gemm512<<<gfull, 512>>>(M1, M1, M3, DD, 0, 0, 0, 0, 0);       // E^2
    k_gemm512<<<gfull, 512>>>(M3, M3, M1, DD, 0, 0, 0, 0, 0);       // E^4
    k_gemm512<<<gfull, 512>>>(M1, M1, M3, DD, 0, 0, 0, 0, 0);       // U = E^8 -> M3

    // Phase 2: time doubling
    k_Ainit<<<2, 1024>>>();
    int nd = 0;
    while ((1 << nd) < n_steps) nd++;
    if (nd > 10) nd = 10;

    float* Bc = M3;   // U
    float* Bn = M1;
    int rows = 2;
    if (nd >= 3) {
        for (int kd = 0; kd + 2 < nd; kd++) {
            int dbl_tiles = (rows + 63) / 64;
            k_sq_dbl512<<<dim3(16, 16 + dbl_tiles), 512>>>(
                Bc, Bn, Ar, Ar + (size_t)rows * DD, rows);
            rows <<= 1;
            float* tmp = Bc; Bc = Bn; Bn = tmp;
        }
        // j = nd-2: doubling only
        k_gemm512<<<dim3(16, (rows + 63) / 64), 512>>>(
            Ar, Bc, Ar + (size_t)rows * DD, rows, 0, 0, 0, 0, 0);
        rows <<= 1;
        // j = nd-1: only col 16 of the new rows is ever read
        k_getcol<<<1, 1024>>>(Bc);
        k_matvec<<<DD, 256>>>(Bc);
        k_gemv<<<rows, 256>>>(rows);
    } else {
        for (int kd = 0; kd < nd; kd++) {
            k_gemm512<<<dim3(16, (rows + 63) / 64), 512>>>(
                Ar, Bc, Ar + (size_t)rows * DD, rows, 0, 0, 0, 0, 0);
            rows <<= 1;
            if (kd < nd - 1) {
                k_gemm512<<<gfull, 512>>>(Bc, Bc, Bn, DD, 0, 0, 0, 0, 0);
                float* tmp = Bc; Bc = Bn; Bn = tmp;
            }
        }
    }

    // Phase 3: extract populations
    k_extract<<<(n_steps + 255) / 256, 256>>>((float*)d_out, n_steps);
}